// round 9
// baseline (speedup 1.0000x reference)
#include <cuda_runtime.h>
#include <cuda_fp16.h>
#include <cstdint>

// Shapes: Q[2,2048,1024], mask[2,2048], W_*[1024,1024], b_*[1024], out[2,2048,1024] fp32
// Scratch (fp16): g_qh,g_kh [bh][s][64]; g_vTh [bh][64(dv)][2048(s)];
//                 g_Ah = fp16 Q-input, g_Wh = fp16 weights
__device__ __align__(16) __half g_qh [2 * 16 * 2048 * 64];
__device__ __align__(16) __half g_kh [2 * 16 * 2048 * 64];
__device__ __align__(16) __half g_vTh[2 * 16 * 64 * 2048];
__device__ __align__(16) __half g_Ah [4096 * 1024];
__device__ __align__(16) __half g_Wh [3][1024 * 1024];

// ---------------------------------------------------------------------------
// helpers
// ---------------------------------------------------------------------------
__device__ __forceinline__ uint32_t packh(float lo, float hi) {
    uint32_t d;
    asm("cvt.rn.f16x2.f32 %0, %1, %2;" : "=r"(d) : "f"(hi), "f"(lo));
    return d;
}
__device__ __forceinline__ uint32_t smem_u32(const void* p) {
    uint32_t a;
    asm("{ .reg .u64 t; cvta.to.shared.u64 t, %1; cvt.u32.u64 %0, t; }" : "=r"(a) : "l"(p));
    return a;
}
__device__ __forceinline__ void ldsm4(uint32_t* r, uint32_t addr) {
    asm volatile("ldmatrix.sync.aligned.m8n8.x4.shared.b16 {%0,%1,%2,%3}, [%4];"
                 : "=r"(r[0]), "=r"(r[1]), "=r"(r[2]), "=r"(r[3]) : "r"(addr));
}
__device__ __forceinline__ void mma16(float* c, const uint32_t* a, const uint32_t* b) {
    asm volatile(
        "mma.sync.aligned.m16n8k16.row.col.f32.f16.f16.f32 "
        "{%0,%1,%2,%3}, {%4,%5,%6,%7}, {%8,%9}, {%0,%1,%2,%3};"
        : "+f"(c[0]), "+f"(c[1]), "+f"(c[2]), "+f"(c[3])
        : "r"(a[0]), "r"(a[1]), "r"(a[2]), "r"(a[3]), "r"(b[0]), "r"(b[1]));
}
__device__ __forceinline__ void cpa16(uint32_t dst, const void* src) {
    asm volatile("cp.async.ca.shared.global [%0], [%1], 16;" :: "r"(dst), "l"(src));
}
#define CP_COMMIT() asm volatile("cp.async.commit_group;" ::: "memory")
#define CP_WAIT1()  asm volatile("cp.async.wait_group 1;" ::: "memory")

// A-operand ldmatrix byte address (16-row x k16 tile)
__device__ __forceinline__ uint32_t a_addr_h(const __half* base, int rowBase, int stride, int lane) {
    const int row = rowBase + ((lane >> 3) & 1) * 8 + (lane & 7);
    const int col = (lane >> 4) << 3;
    return smem_u32(base + row * stride + col);
}
// B-pair ldmatrix byte address -> {r0,r1}=n-group0, {r2,r3}=n-group1
__device__ __forceinline__ uint32_t b_addr_h(const __half* base, int rowBase, int stride, int lane) {
    const int sel = lane >> 3;
    const int row = rowBase + (sel >> 1) * 8 + (lane & 7);
    const int col = (sel & 1) << 3;
    return smem_u32(base + row * stride + col);
}

// ---------------------------------------------------------------------------
// fp16 pre-convert
// ---------------------------------------------------------------------------
__global__ __launch_bounds__(256)
void round_kernel(const float* __restrict__ Qin,
                  const float* __restrict__ Wq,
                  const float* __restrict__ Wk,
                  const float* __restrict__ Wv)
{
    const int i = blockIdx.x * 256 + threadIdx.x;
    const int y = blockIdx.y;
    const float* src;
    __half* dst;
    if (y == 0) { src = Qin; dst = g_Ah; }
    else        { if (i >= 262144) return;
                  src = (y == 1) ? Wq : (y == 2) ? Wk : Wv; dst = g_Wh[y - 1]; }
    const float4 v = ((const float4*)src)[i];
    ((uint2*)dst)[i] = make_uint2(packh(v.x, v.y), packh(v.z, v.w));
}

// ---------------------------------------------------------------------------
// Projection GEMM (fp16 mma): tile M=128 N=128, K-chunk 64 (4 k16 steps),
// cp.async 2-stage, 16 mainloop iterations. 256 thr. grid = (8, 32, 3).
// ---------------------------------------------------------------------------
#define PSTR 72                      // halves per smem row (64 + 8 pad)
#define PSTG_B (256 * PSTR * 2)      // bytes per stage (36864)

__global__ __launch_bounds__(256, 2)
void proj_kernel(const float* __restrict__ bq,
                 const float* __restrict__ bk,
                 const float* __restrict__ bv)
{
    __shared__ __align__(16) __half sbuf[2][256 * PSTR];
    __shared__ float s_bias[128];

    const int proj = blockIdx.z;
    const __half* A = g_Ah;
    const __half* W = g_Wh[proj];
    const float* bias = (proj == 0) ? bq : (proj == 1) ? bk : bv;

    const int tid  = threadIdx.x;
    const int lane = tid & 31;
    const int w    = tid >> 5;
    const int g    = lane >> 2;
    const int cq   = lane & 3;
    const int mw   = (w & 3) << 5;
    const int nw   = (w >> 2) << 6;
    const int m0   = blockIdx.y << 7;
    const int n0   = blockIdx.x << 7;

    if (tid < 128) s_bias[tid] = bias[n0 + tid];

    const uint32_t uS = smem_u32(sbuf);

    const uint32_t aAdr0 = a_addr_h(&sbuf[0][0], mw,      PSTR, lane);
    const uint32_t aAdr1 = a_addr_h(&sbuf[0][0], mw + 16, PSTR, lane);
    uint32_t bAdr[4];
    #pragma unroll
    for (int j = 0; j < 4; j++)
        bAdr[j] = b_addr_h(&sbuf[0][128 * PSTR], nw + 16 * j, PSTR, lane);

    // loader: thread = one row (A rows 0-127, W rows 128-255), 8x16B per stage
    const __half* srcbase = (tid < 128) ? (A + (size_t)(m0 + tid) * 1024)
                                        : (W + (size_t)(n0 + tid - 128) * 1024);
    const uint32_t drow = uS + (uint32_t)(tid * PSTR) * 2;

    float acc[2][8][4] = {};

    #pragma unroll
    for (int st = 0; st < 2; st++) {
        const int k0 = st << 6;
        #pragma unroll
        for (int i = 0; i < 8; i++)
            cpa16(drow + st * PSTG_B + i * 16, srcbase + k0 + i * 8);
        CP_COMMIT();
    }

    for (int c = 0; c < 16; ++c) {
        const int st = c & 1;
        const uint32_t stoff = (uint32_t)st * PSTG_B;
        CP_WAIT1();
        __syncthreads();

        #pragma unroll
        for (int ks = 0; ks < 4; ++ks) {
            const uint32_t koff = stoff + (uint32_t)(ks << 5);
            uint32_t a0[4], a1[4];
            ldsm4(a0, aAdr0 + koff);
            ldsm4(a1, aAdr1 + koff);
            #pragma unroll
            for (int j = 0; j < 4; j++) {
                uint32_t bb[4];
                ldsm4(bb, bAdr[j] + koff);
                mma16(acc[0][2 * j],     a0, bb);
                mma16(acc[0][2 * j + 1], a0, bb + 2);
                mma16(acc[1][2 * j],     a1, bb);
                mma16(acc[1][2 * j + 1], a1, bb + 2);
            }
        }
        __syncthreads();

        if (c + 2 < 16) {
            const int k0 = (c + 2) << 6;
            #pragma unroll
            for (int i = 0; i < 8; i++)
                cpa16(drow + stoff + i * 16, srcbase + k0 + i * 8);
        }
        CP_COMMIT();
    }

    // ---- epilogue (fp16 stores) ----
    const int h = (n0 + nw) >> 6;
    #pragma unroll
    for (int mt = 0; mt < 2; mt++) {
        const int m  = m0 + mw + (mt << 4) + g;
        const int b_ = m >> 11;
        const int s  = m & 2047;
        const int bh = b_ * 16 + h;
        #pragma unroll
        for (int nt = 0; nt < 8; nt++) {
            const int col  = nw + (nt << 3) + (cq << 1);
            const int colh = col & 63;
            const float b0 = s_bias[col], b1 = s_bias[col + 1];
            if (proj < 2) {
                __half* dst = (proj == 0) ? g_qh : g_kh;
                *(uint32_t*)&dst[(size_t)(bh * 2048 + s) * 64 + colh] =
                    packh(acc[mt][nt][0] + b0, acc[mt][nt][1] + b1);
                *(uint32_t*)&dst[(size_t)(bh * 2048 + s + 8) * 64 + colh] =
                    packh(acc[mt][nt][2] + b0, acc[mt][nt][3] + b1);
            } else {
                g_vTh[(size_t)(bh * 64 + colh)     * 2048 + s]     = __float2half_rn(acc[mt][nt][0] + b0);
                g_vTh[(size_t)(bh * 64 + colh + 1) * 2048 + s]     = __float2half_rn(acc[mt][nt][1] + b1);
                g_vTh[(size_t)(bh * 64 + colh)     * 2048 + s + 8] = __float2half_rn(acc[mt][nt][2] + b0);
                g_vTh[(size_t)(bh * 64 + colh + 1) * 2048 + s + 8] = __float2half_rn(acc[mt][nt][3] + b1);
            }
        }
    }
}

// ---------------------------------------------------------------------------
// Attention v7 (fp16): 128 thr, warp = 32q x 64 keys, 3 blocks/SM.
// Q fragments re-loaded from smem each kt (cheap LSU) to fit the 168-reg cap.
// ---------------------------------------------------------------------------
#define HSTR 72
#define KSTG_B (64 * HSTR * 2)
#define ATTN_SMEM_BYTES (128 * HSTR * 2 + 4 * KSTG_B + 2 * 64 * 4)

__global__ __launch_bounds__(128, 3)
void attn_kernel(const float* __restrict__ mask, float* __restrict__ out)
{
    extern __shared__ __align__(16) __half smh[];
    __half* Qs = smh;                        // [128 q][72]
    __half* Ks = smh + 128 * HSTR;           // [2][64 key][72]
    __half* Vs = Ks + 2 * 64 * HSTR;         // [2][64 dv][72]
    float* maskS = (float*)(Vs + 2 * 64 * HSTR);   // [2][64]

    const int tid  = threadIdx.x;
    const int lane = tid & 31;
    const int w    = tid >> 5;
    const int g    = lane >> 2;
    const int cq   = lane & 3;
    const int qw   = w << 5;
    const int q0   = blockIdx.x << 7;
    const int bh   = blockIdx.y;
    const int b    = bh >> 4;
    const int h    = bh & 15;

    const uint32_t uQ = smem_u32(Qs);
    const uint32_t uK = smem_u32(Ks);
    const uint32_t uV = smem_u32(Vs);
    const uint32_t uM = smem_u32(maskS);

    const uint32_t qAdr0 = a_addr_h(Qs, qw,      HSTR, lane);
    const uint32_t qAdr1 = a_addr_h(Qs, qw + 16, HSTR, lane);
    uint32_t kAdr[4], vAdr[4];
    #pragma unroll
    for (int j = 0; j < 4; j++) {
        kAdr[j] = b_addr_h(Ks, 16 * j, HSTR, lane);
        vAdr[j] = b_addr_h(Vs, 16 * j, HSTR, lane);
    }

    const int r2 = tid >> 1;
    const int sB = (tid & 1) * 64;

    // ---- preload: Q + K/V tiles 0,1 + mask ----
    #pragma unroll
    for (int i = 0; i < 8; i++)
        cpa16(uQ + (uint32_t)(tid * HSTR) * 2 + i * 16,
              g_qh + (size_t)(bh * 2048 + q0 + tid) * 64 + i * 8);
    #pragma unroll
    for (int i = 0; i < 4; i++) {
        cpa16(uK + (uint32_t)(r2 * HSTR) * 2 + sB + i * 16,
              g_kh + (size_t)(bh * 2048 + r2) * 64 + (sB >> 1) + i * 8);
        cpa16(uV + (uint32_t)(r2 * HSTR) * 2 + sB + i * 16,
              g_vTh + (size_t)(bh * 64 + r2) * 2048 + (sB >> 1) + i * 8);
    }
    if (tid < 16) cpa16(uM + tid * 16, mask + b * 2048 + tid * 4);
    CP_COMMIT();
    #pragma unroll
    for (int i = 0; i < 4; i++) {
        cpa16(uK + KSTG_B + (uint32_t)(r2 * HSTR) * 2 + sB + i * 16,
              g_kh + (size_t)(bh * 2048 + 64 + r2) * 64 + (sB >> 1) + i * 8);
        cpa16(uV + KSTG_B + (uint32_t)(r2 * HSTR) * 2 + sB + i * 16,
              g_vTh + (size_t)(bh * 64 + r2) * 2048 + 64 + (sB >> 1) + i * 8);
    }
    if (tid < 16) cpa16(uM + 256 + tid * 16, mask + b * 2048 + 64 + tid * 4);
    CP_COMMIT();
    CP_WAIT1();
    __syncthreads();

    float acc[16][4] = {};
    float rs[4] = {};

    for (int kt = 0; kt < 32; kt++) {
        const int cur = kt & 1;
        const uint32_t stoff = (uint32_t)cur * KSTG_B;

        // ---- S = Q K^T : 4 k16 steps over dk (Q frags from smem) ----
        float s[16][4] = {};
        #pragma unroll
        for (int ks = 0; ks < 4; ks++) {
            const uint32_t koff = (uint32_t)(ks << 5);
            uint32_t a0[4], a1[4];
            ldsm4(a0, qAdr0 + koff);
            ldsm4(a1, qAdr1 + koff);
            #pragma unroll
            for (int j = 0; j < 4; j++) {
                uint32_t bb[4];
                ldsm4(bb, kAdr[j] + stoff + koff);
                mma16(s[2 * j],         a0, bb);
                mma16(s[2 * j + 1],     a0, bb + 2);
                mma16(s[8 + 2 * j],     a1, bb);
                mma16(s[8 + 2 * j + 1], a1, bb + 2);
            }
        }

        // ---- P = exp(S/8)*mask; unrounded row sums ----
        #pragma unroll
        for (int mt = 0; mt < 2; mt++) {
            #pragma unroll
            for (int nt = 0; nt < 8; nt++) {
                const int idx = mt * 8 + nt;
                const float2 mm = *(const float2*)&maskS[cur * 64 + (nt << 3) + (cq << 1)];
                const float p00 = __expf(s[idx][0] * 0.125f) * mm.x;
                const float p01 = __expf(s[idx][1] * 0.125f) * mm.y;
                const float p10 = __expf(s[idx][2] * 0.125f) * mm.x;
                const float p11 = __expf(s[idx][3] * 0.125f) * mm.y;
                rs[mt * 2 + 0] += p00 + p01;
                rs[mt * 2 + 1] += p10 + p11;
                s[idx][0] = p00; s[idx][1] = p01; s[idx][2] = p10; s[idx][3] = p11;
            }
        }

        // ---- acc += P @ V : A = f16x2 packs of s (native pairing) ----
        #pragma unroll
        for (int t = 0; t < 4; t++) {
            const uint32_t koff = stoff + (uint32_t)(t << 5);
            uint32_t a0[4] = { packh(s[2*t][0],   s[2*t][1]),   packh(s[2*t][2],   s[2*t][3]),
                               packh(s[2*t+1][0], s[2*t+1][1]), packh(s[2*t+1][2], s[2*t+1][3]) };
            uint32_t a1[4] = { packh(s[8+2*t][0],   s[8+2*t][1]),   packh(s[8+2*t][2],   s[8+2*t][3]),
                               packh(s[8+2*t+1][0], s[8+2*t+1][1]), packh(s[8+2*t+1][2], s[8+2*t+1][3]) };
            #pragma unroll
            for (int j = 0; j < 4; j++) {
                uint32_t bb[4];
                ldsm4(bb, vAdr[j] + koff);
                mma16(acc[2 * j],         a0, bb);
                mma16(acc[2 * j + 1],     a0, bb + 2);
                mma16(acc[8 + 2 * j],     a1, bb);
                mma16(acc[8 + 2 * j + 1], a1, bb + 2);
            }
        }

        // ---- pipeline refill (tile kt+2) ----
        __syncthreads();
        if (kt + 2 < 32) {
            const int kn = (kt + 2) << 6;
            #pragma unroll
            for (int i = 0; i < 4; i++) {
                cpa16(uK + stoff + (uint32_t)(r2 * HSTR) * 2 + sB + i * 16,
                      g_kh + (size_t)(bh * 2048 + kn + r2) * 64 + (sB >> 1) + i * 8);
                cpa16(uV + stoff + (uint32_t)(r2 * HSTR) * 2 + sB + i * 16,
                      g_vTh + (size_t)(bh * 64 + r2) * 2048 + kn + (sB >> 1) + i * 8);
            }
            if (tid < 16) cpa16(uM + cur * 256 + tid * 16, mask + b * 2048 + kn + tid * 4);
        }
        CP_COMMIT();
        CP_WAIT1();
        __syncthreads();
    }

    // ---- denominator ----
    #pragma unroll
    for (int i = 0; i < 4; i++) {
        rs[i] += __shfl_xor_sync(0xffffffffu, rs[i], 1);
        rs[i] += __shfl_xor_sync(0xffffffffu, rs[i], 2);
        rs[i] = 1.0f / (rs[i] + 1e-8f);
    }

    #pragma unroll
    for (int mt = 0; mt < 2; mt++) {
        const int q_lo = q0 + qw + (mt << 4) + g;
        #pragma unroll
        for (int nt = 0; nt < 8; nt++) {
            const int idx = mt * 8 + nt;
            const int dv = (nt << 3) + (cq << 1);
            *(float2*)&out[(size_t)((b * 2048 + q_lo) * 16 + h) * 64 + dv] =
                make_float2(acc[idx][0] * rs[mt * 2], acc[idx][1] * rs[mt * 2]);
            *(float2*)&out[(size_t)((b * 2048 + q_lo + 8) * 16 + h) * 64 + dv] =
                make_float2(acc[idx][2] * rs[mt * 2 + 1], acc[idx][3] * rs[mt * 2 + 1]);
        }
    }
}

// ---------------------------------------------------------------------------
extern "C" void kernel_launch(void* const* d_in, const int* in_sizes, int n_in,
                              void* d_out, int out_size)
{
    const float* Q    = (const float*)d_in[0];
    const float* mask = (const float*)d_in[1];
    const float* Wq   = (const float*)d_in[2];
    const float* bq   = (const float*)d_in[3];
    const float* Wk   = (const float*)d_in[4];
    const float* bk   = (const float*)d_in[5];
    const float* Wv   = (const float*)d_in[6];
    const float* bv   = (const float*)d_in[7];
    float* out = (float*)d_out;

    cudaFuncSetAttribute(attn_kernel,
                         cudaFuncAttributeMaxDynamicSharedMemorySize, ATTN_SMEM_BYTES);

    round_kernel<<<dim3(4096, 4), 256>>>(Q, Wq, Wk, Wv);
    proj_kernel<<<dim3(8, 32, 3), 256>>>(bq, bk, bv);
    attn_kernel<<<dim3(16, 32), 128, ATTN_SMEM_BYTES>>>(mask, out);
}